// round 1
// baseline (speedup 1.0000x reference)
#include <cuda_runtime.h>

// ---------------------------------------------------------------------------
// Problem constants
// ---------------------------------------------------------------------------
#define N_PFAS 50000
#define N_GW   200000
#define N_SW   20000
#define D      32
#define E_PG   2000000
#define E_GP   2000000
#define E_PS   1000000
#define E_SP   1000000

// Output layout: h_pfas [N_PFAS*32] | y [N_GW] | h_sw [N_SW*32]
#define OFF_Y   (N_PFAS * D)            // 1,600,000
#define OFF_SW  (N_PFAS * D + N_GW)     // 1,800,000

// ---------------------------------------------------------------------------
// Scratch (device globals; allocation-free)
// ---------------------------------------------------------------------------
__device__ float g_sum_pg[(size_t)N_GW * D];     // pfas->gw sums
__device__ float g_cnt_pg[N_GW];
__device__ int   g_maxe_pg[N_GW];

__device__ float g_sum_gp[(size_t)N_PFAS * D];   // gw->pfas sums
__device__ float g_cnt_gp[N_PFAS];
__device__ int   g_maxe_gp[N_PFAS];

__device__ float g_sum_sp[(size_t)N_PFAS * D];   // sw->pfas sums
__device__ float g_cnt_sp[N_PFAS];

__device__ float g_sum_ps[(size_t)N_SW * D];     // pfas->sw sums
__device__ float g_cnt_ps[N_SW];

// ---------------------------------------------------------------------------
// Init: zero sums/counts, set max-edge-id to -1
// ---------------------------------------------------------------------------
__global__ void k_init() {
    int i = blockIdx.x * blockDim.x + threadIdx.x;
    int stride = gridDim.x * blockDim.x;
    for (int j = i; j < N_GW * D;   j += stride) g_sum_pg[j] = 0.f;
    for (int j = i; j < N_PFAS * D; j += stride) g_sum_gp[j] = 0.f;
    for (int j = i; j < N_PFAS * D; j += stride) g_sum_sp[j] = 0.f;
    for (int j = i; j < N_SW * D;   j += stride) g_sum_ps[j] = 0.f;
    for (int j = i; j < N_GW;   j += stride) { g_cnt_pg[j] = 0.f; g_maxe_pg[j] = -1; }
    for (int j = i; j < N_PFAS; j += stride) { g_cnt_gp[j] = 0.f; g_maxe_gp[j] = -1;
                                               g_cnt_sp[j] = 0.f; }
    for (int j = i; j < N_SW;   j += stride) g_cnt_ps[j] = 0.f;
}

// ---------------------------------------------------------------------------
// Edge aggregation: one warp per edge; lane j handles feature j.
//   sum[dst][j] += x_src[src][j];  cnt[dst] += 1;  maxe[dst] = max(maxe, e)
// ---------------------------------------------------------------------------
__global__ void k_agg(const float* __restrict__ xsrc,
                      const int*   __restrict__ src,
                      const int*   __restrict__ dst,
                      float* __restrict__ sum,
                      float* __restrict__ cnt,
                      int*   __restrict__ maxe,   // may be nullptr
                      int E)
{
    long long gid = (long long)blockIdx.x * blockDim.x + threadIdx.x;
    int e    = (int)(gid >> 5);
    int lane = (int)(gid & 31);
    if (e >= E) return;
    int s = __ldg(&src[e]);
    int d = __ldg(&dst[e]);
    float v = __ldg(&xsrc[(size_t)s * D + lane]);
    atomicAdd(&sum[(size_t)d * D + lane], v);
    if (lane == 0) {
        atomicAdd(&cnt[d], 1.0f);
        if (maxe) atomicMax(&maxe[d], e);
    }
}

// ---------------------------------------------------------------------------
// Epilogue helpers: warp-per-node matvecs (32 shuffles per 32x32 matvec).
// ---------------------------------------------------------------------------

// GW epilogue: out = mean_pg@Wl + bl + x_gw@Wr + edge(last-wins) -> relu -> @W_out + b -> PReLU
__global__ void k_fin_gw(const float* __restrict__ x_gw,
                         const float* __restrict__ ea_pg,
                         const float* __restrict__ Wl, const float* __restrict__ bl,
                         const float* __restrict__ Wr, const float* __restrict__ We,
                         const float* __restrict__ be,
                         const float* __restrict__ Wout, const float* __restrict__ bout,
                         const float* __restrict__ aprelu,
                         float* __restrict__ y)
{
    __shared__ float sWl[D * D], sWr[D * D], sWe[3 * D], sbl[D], sbe[D], sWo[D];
    int tid = threadIdx.x;
    for (int j = tid; j < D * D; j += blockDim.x) { sWl[j] = Wl[j]; sWr[j] = Wr[j]; }
    if (tid < 3 * D) sWe[tid] = We[tid];
    if (tid < D) { sbl[tid] = bl[tid]; sbe[tid] = be[tid]; sWo[tid] = Wout[tid]; }
    __syncthreads();

    int node = (blockIdx.x * blockDim.x + tid) >> 5;
    int lane = tid & 31;
    if (node >= N_GW) return;

    float inv = 1.0f / fmaxf(g_cnt_pg[node], 1.0f);
    float m = g_sum_pg[(size_t)node * D + lane] * inv;
    float x = __ldg(&x_gw[(size_t)node * D + lane]);
    float acc = sbl[lane];
#pragma unroll
    for (int k = 0; k < D; k++) {
        acc += __shfl_sync(0xffffffffu, m, k) * sWl[k * D + lane];
        acc += __shfl_sync(0xffffffffu, x, k) * sWr[k * D + lane];
    }
    int me = g_maxe_pg[node];
    if (me >= 0) {
        float e0 = __ldg(&ea_pg[(size_t)me * 3 + 0]);
        float e1 = __ldg(&ea_pg[(size_t)me * 3 + 1]);
        float e2 = __ldg(&ea_pg[(size_t)me * 3 + 2]);
        acc += e0 * sWe[lane] + e1 * sWe[D + lane] + e2 * sWe[2 * D + lane] + sbe[lane];
    }
    float h = fmaxf(acc, 0.0f);
    float p = h * sWo[lane];
#pragma unroll
    for (int o = 16; o > 0; o >>= 1) p += __shfl_xor_sync(0xffffffffu, p, o);
    if (lane == 0) {
        float yv = p + bout[0];
        y[node] = (yv >= 0.0f) ? yv : aprelu[0] * yv;
    }
}

// PFAS epilogue: two relations summed (gp with edge attrs, sp plain), relu.
__global__ void k_fin_pfas(const float* __restrict__ x_pfas,
                           const float* __restrict__ ea_gp,
                           const float* __restrict__ Wl_gp, const float* __restrict__ bl_gp,
                           const float* __restrict__ Wr_gp, const float* __restrict__ We_gp,
                           const float* __restrict__ be_gp,
                           const float* __restrict__ Wl_sp, const float* __restrict__ bl_sp,
                           const float* __restrict__ Wr_sp,
                           float* __restrict__ h_out)
{
    __shared__ float sWlg[D * D], sWls[D * D], sWr[D * D], sWe[3 * D], sb[D], sbe[D];
    int tid = threadIdx.x;
    for (int j = tid; j < D * D; j += blockDim.x) {
        sWlg[j] = Wl_gp[j];
        sWls[j] = Wl_sp[j];
        sWr[j]  = Wr_gp[j] + Wr_sp[j];   // shared x_pfas term: combine weights
    }
    if (tid < 3 * D) sWe[tid] = We_gp[tid];
    if (tid < D) { sb[tid] = bl_gp[tid] + bl_sp[tid]; sbe[tid] = be_gp[tid]; }
    __syncthreads();

    int node = (blockIdx.x * blockDim.x + tid) >> 5;
    int lane = tid & 31;
    if (node >= N_PFAS) return;

    float invg = 1.0f / fmaxf(g_cnt_gp[node], 1.0f);
    float invs = 1.0f / fmaxf(g_cnt_sp[node], 1.0f);
    float mg = g_sum_gp[(size_t)node * D + lane] * invg;
    float ms = g_sum_sp[(size_t)node * D + lane] * invs;
    float x  = __ldg(&x_pfas[(size_t)node * D + lane]);
    float acc = sb[lane];
#pragma unroll
    for (int k = 0; k < D; k++) {
        acc += __shfl_sync(0xffffffffu, mg, k) * sWlg[k * D + lane];
        acc += __shfl_sync(0xffffffffu, ms, k) * sWls[k * D + lane];
        acc += __shfl_sync(0xffffffffu, x,  k) * sWr[k * D + lane];
    }
    int me = g_maxe_gp[node];
    if (me >= 0) {
        float e0 = __ldg(&ea_gp[(size_t)me * 3 + 0]);
        float e1 = __ldg(&ea_gp[(size_t)me * 3 + 1]);
        float e2 = __ldg(&ea_gp[(size_t)me * 3 + 2]);
        acc += e0 * sWe[lane] + e1 * sWe[D + lane] + e2 * sWe[2 * D + lane] + sbe[lane];
    }
    h_out[(size_t)node * D + lane] = fmaxf(acc, 0.0f);
}

// SW epilogue: plain SAGE, relu.
__global__ void k_fin_sw(const float* __restrict__ x_sw,
                         const float* __restrict__ Wl, const float* __restrict__ bl,
                         const float* __restrict__ Wr,
                         float* __restrict__ h_out)
{
    __shared__ float sWl[D * D], sWr[D * D], sbl[D];
    int tid = threadIdx.x;
    for (int j = tid; j < D * D; j += blockDim.x) { sWl[j] = Wl[j]; sWr[j] = Wr[j]; }
    if (tid < D) sbl[tid] = bl[tid];
    __syncthreads();

    int node = (blockIdx.x * blockDim.x + tid) >> 5;
    int lane = tid & 31;
    if (node >= N_SW) return;

    float inv = 1.0f / fmaxf(g_cnt_ps[node], 1.0f);
    float m = g_sum_ps[(size_t)node * D + lane] * inv;
    float x = __ldg(&x_sw[(size_t)node * D + lane]);
    float acc = sbl[lane];
#pragma unroll
    for (int k = 0; k < D; k++) {
        acc += __shfl_sync(0xffffffffu, m, k) * sWl[k * D + lane];
        acc += __shfl_sync(0xffffffffu, x, k) * sWr[k * D + lane];
    }
    h_out[(size_t)node * D + lane] = fmaxf(acc, 0.0f);
}

// ---------------------------------------------------------------------------
// Launch
// ---------------------------------------------------------------------------
extern "C" void kernel_launch(void* const* d_in, const int* in_sizes, int n_in,
                              void* d_out, int out_size)
{
    const float* x_pfas = (const float*)d_in[0];
    const float* x_gw   = (const float*)d_in[1];
    const float* x_sw   = (const float*)d_in[2];
    const int*   src_pg = (const int*)d_in[3];
    const int*   dst_pg = (const int*)d_in[4];
    const float* ea_pg  = (const float*)d_in[5];
    const int*   src_gp = (const int*)d_in[6];
    const int*   dst_gp = (const int*)d_in[7];
    const float* ea_gp  = (const float*)d_in[8];
    const int*   src_ps = (const int*)d_in[9];
    const int*   dst_ps = (const int*)d_in[10];
    const int*   src_sp = (const int*)d_in[11];
    const int*   dst_sp = (const int*)d_in[12];
    const float* Wl_pg  = (const float*)d_in[13];
    const float* bl_pg  = (const float*)d_in[14];
    const float* Wr_pg  = (const float*)d_in[15];
    const float* We_pg  = (const float*)d_in[16];
    const float* be_pg  = (const float*)d_in[17];
    const float* Wl_gp  = (const float*)d_in[18];
    const float* bl_gp  = (const float*)d_in[19];
    const float* Wr_gp  = (const float*)d_in[20];
    const float* We_gp  = (const float*)d_in[21];
    const float* be_gp  = (const float*)d_in[22];
    const float* Wl_ps  = (const float*)d_in[23];
    const float* bl_ps  = (const float*)d_in[24];
    const float* Wr_ps  = (const float*)d_in[25];
    const float* Wl_sp  = (const float*)d_in[26];
    const float* bl_sp  = (const float*)d_in[27];
    const float* Wr_sp  = (const float*)d_in[28];
    const float* W_out  = (const float*)d_in[29];
    const float* b_out  = (const float*)d_in[30];
    const float* a_pre  = (const float*)d_in[31];

    float* out      = (float*)d_out;
    float* out_pfas = out;
    float* out_y    = out + OFF_Y;
    float* out_sw   = out + OFF_SW;

    // scratch pointers (device symbols referenced directly inside kernels)
    float *p_sum_pg, *p_cnt_pg, *p_sum_gp, *p_cnt_gp, *p_sum_sp, *p_cnt_sp, *p_sum_ps, *p_cnt_ps;
    int *p_maxe_pg, *p_maxe_gp;
    cudaGetSymbolAddress((void**)&p_sum_pg, g_sum_pg);
    cudaGetSymbolAddress((void**)&p_cnt_pg, g_cnt_pg);
    cudaGetSymbolAddress((void**)&p_sum_gp, g_sum_gp);
    cudaGetSymbolAddress((void**)&p_cnt_gp, g_cnt_gp);
    cudaGetSymbolAddress((void**)&p_sum_sp, g_sum_sp);
    cudaGetSymbolAddress((void**)&p_cnt_sp, g_cnt_sp);
    cudaGetSymbolAddress((void**)&p_sum_ps, g_sum_ps);
    cudaGetSymbolAddress((void**)&p_cnt_ps, g_cnt_ps);
    cudaGetSymbolAddress((void**)&p_maxe_pg, g_maxe_pg);
    cudaGetSymbolAddress((void**)&p_maxe_gp, g_maxe_gp);

    // 1) init scratch
    k_init<<<2048, 256>>>();

    // 2) edge aggregation (warp per edge)
    {
        long long t;
        t = (long long)E_PG * 32;
        k_agg<<<(unsigned)((t + 255) / 256), 256>>>(x_pfas, src_pg, dst_pg,
                                                    p_sum_pg, p_cnt_pg, p_maxe_pg, E_PG);
        t = (long long)E_GP * 32;
        k_agg<<<(unsigned)((t + 255) / 256), 256>>>(x_gw, src_gp, dst_gp,
                                                    p_sum_gp, p_cnt_gp, p_maxe_gp, E_GP);
        t = (long long)E_SP * 32;
        k_agg<<<(unsigned)((t + 255) / 256), 256>>>(x_sw, src_sp, dst_sp,
                                                    p_sum_sp, p_cnt_sp, (int*)nullptr, E_SP);
        t = (long long)E_PS * 32;
        k_agg<<<(unsigned)((t + 255) / 256), 256>>>(x_pfas, src_ps, dst_ps,
                                                    p_sum_ps, p_cnt_ps, (int*)nullptr, E_PS);
    }

    // 3) fused epilogues (warp per node, 8 nodes per 256-thread block)
    k_fin_gw<<<(N_GW * 32 + 255) / 256, 256>>>(x_gw, ea_pg,
                                               Wl_pg, bl_pg, Wr_pg, We_pg, be_pg,
                                               W_out, b_out, a_pre, out_y);
    k_fin_pfas<<<(N_PFAS * 32 + 255) / 256, 256>>>(x_pfas, ea_gp,
                                                   Wl_gp, bl_gp, Wr_gp, We_gp, be_gp,
                                                   Wl_sp, bl_sp, Wr_sp, out_pfas);
    k_fin_sw<<<(N_SW * 32 + 255) / 256, 256>>>(x_sw, Wl_ps, bl_ps, Wr_ps, out_sw);

    (void)in_sizes; (void)n_in; (void)out_size;
}

// round 2
// speedup vs baseline: 1.9863x; 1.9863x over previous
#include <cuda_runtime.h>

// ---------------------------------------------------------------------------
// Problem constants
// ---------------------------------------------------------------------------
#define N_PFAS 50000
#define N_GW   200000
#define N_SW   20000
#define D      32
#define E_PG   2000000
#define E_GP   2000000
#define E_PS   1000000
#define E_SP   1000000

// Output layout: h_pfas [N_PFAS*32] | y [N_GW] | h_sw [N_SW*32]
#define OFF_Y   (N_PFAS * D)            // 1,600,000
#define OFF_SW  (N_PFAS * D + N_GW)     // 1,800,000

// ---------------------------------------------------------------------------
// Scratch (device globals; allocation-free)
// ---------------------------------------------------------------------------
__device__ float g_sum_pg[(size_t)N_GW * D];     // pfas->gw sums
__device__ float g_cnt_pg[N_GW];
__device__ int   g_maxe_pg[N_GW];

__device__ float g_sum_gp[(size_t)N_PFAS * D];   // gw->pfas sums
__device__ float g_cnt_gp[N_PFAS];
__device__ int   g_maxe_gp[N_PFAS];

__device__ float g_sum_sp[(size_t)N_PFAS * D];   // sw->pfas sums
__device__ float g_cnt_sp[N_PFAS];

__device__ float g_sum_ps[(size_t)N_SW * D];     // pfas->sw sums
__device__ float g_cnt_ps[N_SW];

// ---------------------------------------------------------------------------
// Init: zero sums/counts, set max-edge-id to -1
// ---------------------------------------------------------------------------
__global__ void k_init() {
    int i = blockIdx.x * blockDim.x + threadIdx.x;
    int stride = gridDim.x * blockDim.x;
    for (int j = i; j < N_GW * D;   j += stride) g_sum_pg[j] = 0.f;
    for (int j = i; j < N_PFAS * D; j += stride) g_sum_gp[j] = 0.f;
    for (int j = i; j < N_PFAS * D; j += stride) g_sum_sp[j] = 0.f;
    for (int j = i; j < N_SW * D;   j += stride) g_sum_ps[j] = 0.f;
    for (int j = i; j < N_GW;   j += stride) { g_cnt_pg[j] = 0.f; g_maxe_pg[j] = -1; }
    for (int j = i; j < N_PFAS; j += stride) { g_cnt_gp[j] = 0.f; g_maxe_gp[j] = -1;
                                               g_cnt_sp[j] = 0.f; }
    for (int j = i; j < N_SW;   j += stride) g_cnt_ps[j] = 0.f;
}

// ---------------------------------------------------------------------------
// Vector atomic: red.global.add.v4.f32 (sm_90+)
// ---------------------------------------------------------------------------
__device__ __forceinline__ void red_add_v4(float* addr, float4 v) {
    asm volatile("red.global.add.v4.f32 [%0], {%1,%2,%3,%4};"
                 :: "l"(addr), "f"(v.x), "f"(v.y), "f"(v.z), "f"(v.w)
                 : "memory");
}

// ---------------------------------------------------------------------------
// Edge aggregation: 8 threads per edge; thread handles one float4 segment.
//   sum[dst][seg*4..+3] += x_src[src][seg*4..+3]; cnt[dst]+=1; maxe[dst]=max(.,e)
// ---------------------------------------------------------------------------
__global__ void k_agg(const float* __restrict__ xsrc,
                      const int*   __restrict__ src,
                      const int*   __restrict__ dst,
                      float* __restrict__ sum,
                      float* __restrict__ cnt,
                      int*   __restrict__ maxe,   // may be nullptr
                      int E)
{
    int t = blockIdx.x * blockDim.x + threadIdx.x;
    int e   = t >> 3;
    int seg = t & 7;
    if (e >= E) return;
    int s = __ldg(&src[e]);
    int d = __ldg(&dst[e]);
    float4 v = __ldg(&((const float4*)xsrc)[(size_t)s * 8 + seg]);
    red_add_v4(&sum[(size_t)d * D + seg * 4], v);
    if (seg == 0) {
        atomicAdd(&cnt[d], 1.0f);
        if (maxe) atomicMax(&maxe[d], e);
    }
}

// ---------------------------------------------------------------------------
// Epilogue helpers: warp-per-node matvecs (32 shuffles per 32x32 matvec).
// ---------------------------------------------------------------------------

// GW epilogue: out = mean_pg@Wl + bl + x_gw@Wr + edge(last-wins) -> relu -> @W_out + b -> PReLU
__global__ void k_fin_gw(const float* __restrict__ x_gw,
                         const float* __restrict__ ea_pg,
                         const float* __restrict__ Wl, const float* __restrict__ bl,
                         const float* __restrict__ Wr, const float* __restrict__ We,
                         const float* __restrict__ be,
                         const float* __restrict__ Wout, const float* __restrict__ bout,
                         const float* __restrict__ aprelu,
                         float* __restrict__ y)
{
    __shared__ float sWl[D * D], sWr[D * D], sWe[3 * D], sbl[D], sbe[D], sWo[D];
    int tid = threadIdx.x;
    for (int j = tid; j < D * D; j += blockDim.x) { sWl[j] = Wl[j]; sWr[j] = Wr[j]; }
    if (tid < 3 * D) sWe[tid] = We[tid];
    if (tid < D) { sbl[tid] = bl[tid]; sbe[tid] = be[tid]; sWo[tid] = Wout[tid]; }
    __syncthreads();

    int node = (blockIdx.x * blockDim.x + tid) >> 5;
    int lane = tid & 31;
    if (node >= N_GW) return;

    float inv = 1.0f / fmaxf(g_cnt_pg[node], 1.0f);
    float m = g_sum_pg[(size_t)node * D + lane] * inv;
    float x = __ldg(&x_gw[(size_t)node * D + lane]);
    float acc = sbl[lane];
#pragma unroll
    for (int k = 0; k < D; k++) {
        acc += __shfl_sync(0xffffffffu, m, k) * sWl[k * D + lane];
        acc += __shfl_sync(0xffffffffu, x, k) * sWr[k * D + lane];
    }
    int me = g_maxe_pg[node];
    if (me >= 0) {
        float e0 = __ldg(&ea_pg[(size_t)me * 3 + 0]);
        float e1 = __ldg(&ea_pg[(size_t)me * 3 + 1]);
        float e2 = __ldg(&ea_pg[(size_t)me * 3 + 2]);
        acc += e0 * sWe[lane] + e1 * sWe[D + lane] + e2 * sWe[2 * D + lane] + sbe[lane];
    }
    float h = fmaxf(acc, 0.0f);
    float p = h * sWo[lane];
#pragma unroll
    for (int o = 16; o > 0; o >>= 1) p += __shfl_xor_sync(0xffffffffu, p, o);
    if (lane == 0) {
        float yv = p + bout[0];
        y[node] = (yv >= 0.0f) ? yv : aprelu[0] * yv;
    }
}

// PFAS epilogue: two relations summed (gp with edge attrs, sp plain), relu.
__global__ void k_fin_pfas(const float* __restrict__ x_pfas,
                           const float* __restrict__ ea_gp,
                           const float* __restrict__ Wl_gp, const float* __restrict__ bl_gp,
                           const float* __restrict__ Wr_gp, const float* __restrict__ We_gp,
                           const float* __restrict__ be_gp,
                           const float* __restrict__ Wl_sp, const float* __restrict__ bl_sp,
                           const float* __restrict__ Wr_sp,
                           float* __restrict__ h_out)
{
    __shared__ float sWlg[D * D], sWls[D * D], sWr[D * D], sWe[3 * D], sb[D], sbe[D];
    int tid = threadIdx.x;
    for (int j = tid; j < D * D; j += blockDim.x) {
        sWlg[j] = Wl_gp[j];
        sWls[j] = Wl_sp[j];
        sWr[j]  = Wr_gp[j] + Wr_sp[j];   // shared x_pfas term: combine weights
    }
    if (tid < 3 * D) sWe[tid] = We_gp[tid];
    if (tid < D) { sb[tid] = bl_gp[tid] + bl_sp[tid]; sbe[tid] = be_gp[tid]; }
    __syncthreads();

    int node = (blockIdx.x * blockDim.x + tid) >> 5;
    int lane = tid & 31;
    if (node >= N_PFAS) return;

    float invg = 1.0f / fmaxf(g_cnt_gp[node], 1.0f);
    float invs = 1.0f / fmaxf(g_cnt_sp[node], 1.0f);
    float mg = g_sum_gp[(size_t)node * D + lane] * invg;
    float ms = g_sum_sp[(size_t)node * D + lane] * invs;
    float x  = __ldg(&x_pfas[(size_t)node * D + lane]);
    float acc = sb[lane];
#pragma unroll
    for (int k = 0; k < D; k++) {
        acc += __shfl_sync(0xffffffffu, mg, k) * sWlg[k * D + lane];
        acc += __shfl_sync(0xffffffffu, ms, k) * sWls[k * D + lane];
        acc += __shfl_sync(0xffffffffu, x,  k) * sWr[k * D + lane];
    }
    int me = g_maxe_gp[node];
    if (me >= 0) {
        float e0 = __ldg(&ea_gp[(size_t)me * 3 + 0]);
        float e1 = __ldg(&ea_gp[(size_t)me * 3 + 1]);
        float e2 = __ldg(&ea_gp[(size_t)me * 3 + 2]);
        acc += e0 * sWe[lane] + e1 * sWe[D + lane] + e2 * sWe[2 * D + lane] + sbe[lane];
    }
    h_out[(size_t)node * D + lane] = fmaxf(acc, 0.0f);
}

// SW epilogue: plain SAGE, relu.
__global__ void k_fin_sw(const float* __restrict__ x_sw,
                         const float* __restrict__ Wl, const float* __restrict__ bl,
                         const float* __restrict__ Wr,
                         float* __restrict__ h_out)
{
    __shared__ float sWl[D * D], sWr[D * D], sbl[D];
    int tid = threadIdx.x;
    for (int j = tid; j < D * D; j += blockDim.x) { sWl[j] = Wl[j]; sWr[j] = Wr[j]; }
    if (tid < D) sbl[tid] = bl[tid];
    __syncthreads();

    int node = (blockIdx.x * blockDim.x + tid) >> 5;
    int lane = tid & 31;
    if (node >= N_SW) return;

    float inv = 1.0f / fmaxf(g_cnt_ps[node], 1.0f);
    float m = g_sum_ps[(size_t)node * D + lane] * inv;
    float x = __ldg(&x_sw[(size_t)node * D + lane]);
    float acc = sbl[lane];
#pragma unroll
    for (int k = 0; k < D; k++) {
        acc += __shfl_sync(0xffffffffu, m, k) * sWl[k * D + lane];
        acc += __shfl_sync(0xffffffffu, x, k) * sWr[k * D + lane];
    }
    h_out[(size_t)node * D + lane] = fmaxf(acc, 0.0f);
}

// ---------------------------------------------------------------------------
// Launch
// ---------------------------------------------------------------------------
extern "C" void kernel_launch(void* const* d_in, const int* in_sizes, int n_in,
                              void* d_out, int out_size)
{
    const float* x_pfas = (const float*)d_in[0];
    const float* x_gw   = (const float*)d_in[1];
    const float* x_sw   = (const float*)d_in[2];
    const int*   src_pg = (const int*)d_in[3];
    const int*   dst_pg = (const int*)d_in[4];
    const float* ea_pg  = (const float*)d_in[5];
    const int*   src_gp = (const int*)d_in[6];
    const int*   dst_gp = (const int*)d_in[7];
    const float* ea_gp  = (const float*)d_in[8];
    const int*   src_ps = (const int*)d_in[9];
    const int*   dst_ps = (const int*)d_in[10];
    const int*   src_sp = (const int*)d_in[11];
    const int*   dst_sp = (const int*)d_in[12];
    const float* Wl_pg  = (const float*)d_in[13];
    const float* bl_pg  = (const float*)d_in[14];
    const float* Wr_pg  = (const float*)d_in[15];
    const float* We_pg  = (const float*)d_in[16];
    const float* be_pg  = (const float*)d_in[17];
    const float* Wl_gp  = (const float*)d_in[18];
    const float* bl_gp  = (const float*)d_in[19];
    const float* Wr_gp  = (const float*)d_in[20];
    const float* We_gp  = (const float*)d_in[21];
    const float* be_gp  = (const float*)d_in[22];
    const float* Wl_ps  = (const float*)d_in[23];
    const float* bl_ps  = (const float*)d_in[24];
    const float* Wr_ps  = (const float*)d_in[25];
    const float* Wl_sp  = (const float*)d_in[26];
    const float* bl_sp  = (const float*)d_in[27];
    const float* Wr_sp  = (const float*)d_in[28];
    const float* W_out  = (const float*)d_in[29];
    const float* b_out  = (const float*)d_in[30];
    const float* a_pre  = (const float*)d_in[31];

    float* out      = (float*)d_out;
    float* out_pfas = out;
    float* out_y    = out + OFF_Y;
    float* out_sw   = out + OFF_SW;

    float *p_sum_pg, *p_cnt_pg, *p_sum_gp, *p_cnt_gp, *p_sum_sp, *p_cnt_sp, *p_sum_ps, *p_cnt_ps;
    int *p_maxe_pg, *p_maxe_gp;
    cudaGetSymbolAddress((void**)&p_sum_pg, g_sum_pg);
    cudaGetSymbolAddress((void**)&p_cnt_pg, g_cnt_pg);
    cudaGetSymbolAddress((void**)&p_sum_gp, g_sum_gp);
    cudaGetSymbolAddress((void**)&p_cnt_gp, g_cnt_gp);
    cudaGetSymbolAddress((void**)&p_sum_sp, g_sum_sp);
    cudaGetSymbolAddress((void**)&p_cnt_sp, g_cnt_sp);
    cudaGetSymbolAddress((void**)&p_sum_ps, g_sum_ps);
    cudaGetSymbolAddress((void**)&p_cnt_ps, g_cnt_ps);
    cudaGetSymbolAddress((void**)&p_maxe_pg, g_maxe_pg);
    cudaGetSymbolAddress((void**)&p_maxe_gp, g_maxe_gp);

    // 1) init scratch
    k_init<<<2048, 256>>>();

    // 2) edge aggregation (8 threads per edge, float4 path)
    {
        long long t;
        t = (long long)E_PG * 8;
        k_agg<<<(unsigned)((t + 255) / 256), 256>>>(x_pfas, src_pg, dst_pg,
                                                    p_sum_pg, p_cnt_pg, p_maxe_pg, E_PG);
        t = (long long)E_GP * 8;
        k_agg<<<(unsigned)((t + 255) / 256), 256>>>(x_gw, src_gp, dst_gp,
                                                    p_sum_gp, p_cnt_gp, p_maxe_gp, E_GP);
        t = (long long)E_SP * 8;
        k_agg<<<(unsigned)((t + 255) / 256), 256>>>(x_sw, src_sp, dst_sp,
                                                    p_sum_sp, p_cnt_sp, (int*)nullptr, E_SP);
        t = (long long)E_PS * 8;
        k_agg<<<(unsigned)((t + 255) / 256), 256>>>(x_pfas, src_ps, dst_ps,
                                                    p_sum_ps, p_cnt_ps, (int*)nullptr, E_PS);
    }

    // 3) fused epilogues (warp per node, 8 nodes per 256-thread block)
    k_fin_gw<<<(N_GW * 32 + 255) / 256, 256>>>(x_gw, ea_pg,
                                               Wl_pg, bl_pg, Wr_pg, We_pg, be_pg,
                                               W_out, b_out, a_pre, out_y);
    k_fin_pfas<<<(N_PFAS * 32 + 255) / 256, 256>>>(x_pfas, ea_gp,
                                                   Wl_gp, bl_gp, Wr_gp, We_gp, be_gp,
                                                   Wl_sp, bl_sp, Wr_sp, out_pfas);
    k_fin_sw<<<(N_SW * 32 + 255) / 256, 256>>>(x_sw, Wl_ps, bl_ps, Wr_ps, out_sw);

    (void)in_sizes; (void)n_in; (void)out_size;
}

// round 3
// speedup vs baseline: 3.0476x; 1.5343x over previous
#include <cuda_runtime.h>

// ---------------------------------------------------------------------------
// Problem constants
// ---------------------------------------------------------------------------
#define N_PFAS 50000
#define N_GW   200000
#define N_SW   20000
#define D      32
#define E_PG   2000000
#define E_GP   2000000
#define E_PS   1000000
#define E_SP   1000000

// Output layout: h_pfas [N_PFAS*32] | y [N_GW] | h_sw [N_SW*32]
#define OFF_Y   (N_PFAS * D)
#define OFF_SW  (N_PFAS * D + N_GW)

typedef unsigned long long u64;

// ---------------------------------------------------------------------------
// Scratch (device globals; allocation-free). 16B aligned for v4 atomics/loads.
// ---------------------------------------------------------------------------
__device__ __align__(16) float g_sum_pg[(size_t)N_GW * D];
__device__ float g_cnt_pg[N_GW];
__device__ int   g_maxe_pg[N_GW];

__device__ __align__(16) float g_sum_gp[(size_t)N_PFAS * D];
__device__ float g_cnt_gp[N_PFAS];
__device__ int   g_maxe_gp[N_PFAS];

__device__ __align__(16) float g_sum_sp[(size_t)N_PFAS * D];
__device__ float g_cnt_sp[N_PFAS];

__device__ __align__(16) float g_sum_ps[(size_t)N_SW * D];
__device__ float g_cnt_ps[N_SW];

// ---------------------------------------------------------------------------
// Packed f32x2 helpers (sm_100+)
// ---------------------------------------------------------------------------
__device__ __forceinline__ u64 pk2(float x) {
    u64 d; unsigned xi = __float_as_uint(x);
    asm("mov.b64 %0, {%1, %1};" : "=l"(d) : "r"(xi));
    return d;
}
__device__ __forceinline__ u64 pk2f(float a, float b) {
    u64 d; unsigned ai = __float_as_uint(a), bi = __float_as_uint(b);
    asm("mov.b64 %0, {%1, %2};" : "=l"(d) : "r"(ai), "r"(bi));
    return d;
}
__device__ __forceinline__ u64 f2fma(u64 a, u64 b, u64 c) {
    u64 d; asm("fma.rn.f32x2 %0, %1, %2, %3;" : "=l"(d) : "l"(a), "l"(b), "l"(c));
    return d;
}
__device__ __forceinline__ u64 f2add(u64 a, u64 b) {
    u64 d; asm("add.rn.f32x2 %0, %1, %2;" : "=l"(d) : "l"(a), "l"(b));
    return d;
}
__device__ __forceinline__ float2 up2(u64 a) {
    unsigned lo, hi;
    asm("mov.b64 {%0, %1}, %2;" : "=r"(lo), "=r"(hi) : "l"(a));
    return make_float2(__uint_as_float(lo), __uint_as_float(hi));
}

// ---------------------------------------------------------------------------
// Vector atomic: red.global.add.v4.f32 (sm_90+)
// ---------------------------------------------------------------------------
__device__ __forceinline__ void red_add_v4(float* addr, float4 v) {
    asm volatile("red.global.add.v4.f32 [%0], {%1,%2,%3,%4};"
                 :: "l"(addr), "f"(v.x), "f"(v.y), "f"(v.z), "f"(v.w)
                 : "memory");
}

// ---------------------------------------------------------------------------
// Init
// ---------------------------------------------------------------------------
__global__ void k_init() {
    int i = blockIdx.x * blockDim.x + threadIdx.x;
    int stride = gridDim.x * blockDim.x;
    for (int j = i; j < N_GW * D;   j += stride) g_sum_pg[j] = 0.f;
    for (int j = i; j < N_PFAS * D; j += stride) g_sum_gp[j] = 0.f;
    for (int j = i; j < N_PFAS * D; j += stride) g_sum_sp[j] = 0.f;
    for (int j = i; j < N_SW * D;   j += stride) g_sum_ps[j] = 0.f;
    for (int j = i; j < N_GW;   j += stride) { g_cnt_pg[j] = 0.f; g_maxe_pg[j] = -1; }
    for (int j = i; j < N_PFAS; j += stride) { g_cnt_gp[j] = 0.f; g_maxe_gp[j] = -1;
                                               g_cnt_sp[j] = 0.f; }
    for (int j = i; j < N_SW;   j += stride) g_cnt_ps[j] = 0.f;
}

// ---------------------------------------------------------------------------
// Fused edge aggregation: all 4 relations in one launch.
// 8 lanes per edge-group; each group processes 4 consecutive edges (ILP=4).
// ---------------------------------------------------------------------------
struct AggArgs {
    const float4* x[4];
    const int4*   src[4];
    const int4*   dst[4];
    float*        sum[4];
    float*        cnt[4];
    int*          maxe[4];   // null where unused
    int           ngroups[4];
    int           blkEnd[4]; // exclusive prefix sum of blocks
};

__global__ void k_agg_all(AggArgs A) {
    int b = blockIdx.x;
    int r, base;
    if (b < A.blkEnd[0])      { r = 0; base = 0; }
    else if (b < A.blkEnd[1]) { r = 1; base = A.blkEnd[0]; }
    else if (b < A.blkEnd[2]) { r = 2; base = A.blkEnd[1]; }
    else                      { r = 3; base = A.blkEnd[2]; }

    int t   = (b - base) * blockDim.x + threadIdx.x;
    int g   = t >> 3;
    int seg = t & 7;
    if (g >= A.ngroups[r]) return;

    int4 s4 = __ldg(&A.src[r][g]);
    int4 d4 = __ldg(&A.dst[r][g]);
    const float4* X = A.x[r];
    float* S = A.sum[r];

    float4 v0 = __ldg(&X[(size_t)s4.x * 8 + seg]);
    float4 v1 = __ldg(&X[(size_t)s4.y * 8 + seg]);
    float4 v2 = __ldg(&X[(size_t)s4.z * 8 + seg]);
    float4 v3 = __ldg(&X[(size_t)s4.w * 8 + seg]);

    red_add_v4(&S[(size_t)d4.x * D + seg * 4], v0);
    red_add_v4(&S[(size_t)d4.y * D + seg * 4], v1);
    red_add_v4(&S[(size_t)d4.z * D + seg * 4], v2);
    red_add_v4(&S[(size_t)d4.w * D + seg * 4], v3);

    if (seg == 0) {
        float* C = A.cnt[r];
        atomicAdd(&C[d4.x], 1.0f);
        atomicAdd(&C[d4.y], 1.0f);
        atomicAdd(&C[d4.z], 1.0f);
        atomicAdd(&C[d4.w], 1.0f);
        int* M = A.maxe[r];
        if (M) {
            int e0 = g * 4;
            atomicMax(&M[d4.x], e0);
            atomicMax(&M[d4.y], e0 + 1);
            atomicMax(&M[d4.z], e0 + 2);
            atomicMax(&M[d4.w], e0 + 3);
        }
    }
}

// ---------------------------------------------------------------------------
// Thread-per-node fused epilogues (f32x2 matvecs, no shuffles)
// ---------------------------------------------------------------------------
__device__ __forceinline__ void load_row(const float* base, int n, float inv, float x[32]) {
    const float4* r4 = (const float4*)(base + (size_t)n * D);
#pragma unroll
    for (int q = 0; q < 8; q++) {
        float4 v = __ldg(&r4[q]);
        x[q * 4 + 0] = v.x * inv; x[q * 4 + 1] = v.y * inv;
        x[q * 4 + 2] = v.z * inv; x[q * 4 + 3] = v.w * inv;
    }
}

__device__ __forceinline__ void mv_acc(const float* sW, const float x[32], u64 acc[16]) {
#pragma unroll
    for (int k = 0; k < 32; k++) {
        u64 xk = pk2(x[k]);
        const u64* w2 = (const u64*)(sW + k * 32);
#pragma unroll
        for (int jj = 0; jj < 16; jj++) acc[jj] = f2fma(xk, w2[jj], acc[jj]);
    }
}

// GW: h = relu(mean_pg@Wl + bl + x@Wr + edge) ; y = h@Wo + b ; PReLU
__global__ void __launch_bounds__(256) k_fin_gw(
        const float* __restrict__ x_gw, const float* __restrict__ ea,
        const float* __restrict__ Wl, const float* __restrict__ bl,
        const float* __restrict__ Wr, const float* __restrict__ We,
        const float* __restrict__ be, const float* __restrict__ Wo,
        const float* __restrict__ bout, const float* __restrict__ apre,
        float* __restrict__ y)
{
    __shared__ __align__(16) float sWl[1024], sWr[1024];
    __shared__ __align__(16) float sWe[96];
    __shared__ float sbl[32], sbe[32], sWo[32];
    int tid = threadIdx.x;
    for (int j = tid; j < 1024; j += 256) { sWl[j] = Wl[j]; sWr[j] = Wr[j]; }
    if (tid < 96) sWe[tid] = We[tid];
    if (tid < 32) { sbl[tid] = bl[tid]; sbe[tid] = be[tid]; sWo[tid] = Wo[tid]; }
    __syncthreads();

    int n = blockIdx.x * 256 + tid;
    if (n >= N_GW) return;

    u64 acc[16];
#pragma unroll
    for (int jj = 0; jj < 16; jj++) acc[jj] = pk2f(sbl[2 * jj], sbl[2 * jj + 1]);

    float inv = 1.0f / fmaxf(g_cnt_pg[n], 1.0f);
    float xr[32];
    load_row(g_sum_pg, n, inv, xr);
    mv_acc(sWl, xr, acc);
    load_row(x_gw, n, 1.0f, xr);
    mv_acc(sWr, xr, acc);

    int me = g_maxe_pg[n];
    if (me >= 0) {
        u64 e0 = pk2(__ldg(&ea[3 * (size_t)me + 0]));
        u64 e1 = pk2(__ldg(&ea[3 * (size_t)me + 1]));
        u64 e2 = pk2(__ldg(&ea[3 * (size_t)me + 2]));
        const u64* w0 = (const u64*)(sWe);
        const u64* w1 = (const u64*)(sWe + 32);
        const u64* w2 = (const u64*)(sWe + 64);
#pragma unroll
        for (int jj = 0; jj < 16; jj++) {
            u64 a = acc[jj];
            a = f2fma(e0, w0[jj], a);
            a = f2fma(e1, w1[jj], a);
            a = f2fma(e2, w2[jj], a);
            a = f2add(a, pk2f(sbe[2 * jj], sbe[2 * jj + 1]));
            acc[jj] = a;
        }
    }

    float yv = 0.0f;
#pragma unroll
    for (int jj = 0; jj < 16; jj++) {
        float2 h = up2(acc[jj]);
        yv += fmaxf(h.x, 0.0f) * sWo[2 * jj] + fmaxf(h.y, 0.0f) * sWo[2 * jj + 1];
    }
    yv += __ldg(&bout[0]);
    float a_ = __ldg(&apre[0]);
    y[n] = (yv >= 0.0f) ? yv : a_ * yv;
}

// PFAS: h = relu(mean_gp@Wl_gp + mean_sp@Wl_sp + x@(Wr_gp+Wr_sp) + biases + edge_gp)
__global__ void __launch_bounds__(256) k_fin_pfas(
        const float* __restrict__ x_pfas, const float* __restrict__ ea,
        const float* __restrict__ Wl_gp, const float* __restrict__ bl_gp,
        const float* __restrict__ Wr_gp, const float* __restrict__ We_gp,
        const float* __restrict__ be_gp,
        const float* __restrict__ Wl_sp, const float* __restrict__ bl_sp,
        const float* __restrict__ Wr_sp,
        float* __restrict__ h_out)
{
    __shared__ __align__(16) float sWlg[1024], sWls[1024], sWr[1024];
    __shared__ __align__(16) float sWe[96];
    __shared__ float sb[32], sbe[32];
    int tid = threadIdx.x;
    for (int j = tid; j < 1024; j += 256) {
        sWlg[j] = Wl_gp[j];
        sWls[j] = Wl_sp[j];
        sWr[j]  = Wr_gp[j] + Wr_sp[j];
    }
    if (tid < 96) sWe[tid] = We_gp[tid];
    if (tid < 32) { sb[tid] = bl_gp[tid] + bl_sp[tid]; sbe[tid] = be_gp[tid]; }
    __syncthreads();

    int n = blockIdx.x * 256 + tid;
    if (n >= N_PFAS) return;

    u64 acc[16];
#pragma unroll
    for (int jj = 0; jj < 16; jj++) acc[jj] = pk2f(sb[2 * jj], sb[2 * jj + 1]);

    float invg = 1.0f / fmaxf(g_cnt_gp[n], 1.0f);
    float invs = 1.0f / fmaxf(g_cnt_sp[n], 1.0f);
    float xr[32];
    load_row(g_sum_gp, n, invg, xr);
    mv_acc(sWlg, xr, acc);
    load_row(g_sum_sp, n, invs, xr);
    mv_acc(sWls, xr, acc);
    load_row(x_pfas, n, 1.0f, xr);
    mv_acc(sWr, xr, acc);

    int me = g_maxe_gp[n];
    if (me >= 0) {
        u64 e0 = pk2(__ldg(&ea[3 * (size_t)me + 0]));
        u64 e1 = pk2(__ldg(&ea[3 * (size_t)me + 1]));
        u64 e2 = pk2(__ldg(&ea[3 * (size_t)me + 2]));
        const u64* w0 = (const u64*)(sWe);
        const u64* w1 = (const u64*)(sWe + 32);
        const u64* w2 = (const u64*)(sWe + 64);
#pragma unroll
        for (int jj = 0; jj < 16; jj++) {
            u64 a = acc[jj];
            a = f2fma(e0, w0[jj], a);
            a = f2fma(e1, w1[jj], a);
            a = f2fma(e2, w2[jj], a);
            a = f2add(a, pk2f(sbe[2 * jj], sbe[2 * jj + 1]));
            acc[jj] = a;
        }
    }

    float4* o4 = (float4*)(h_out + (size_t)n * D);
#pragma unroll
    for (int q = 0; q < 8; q++) {
        float2 a = up2(acc[2 * q]);
        float2 b = up2(acc[2 * q + 1]);
        o4[q] = make_float4(fmaxf(a.x, 0.f), fmaxf(a.y, 0.f),
                            fmaxf(b.x, 0.f), fmaxf(b.y, 0.f));
    }
}

// SW: h = relu(mean_ps@Wl + bl + x@Wr)
__global__ void __launch_bounds__(256) k_fin_sw(
        const float* __restrict__ x_sw,
        const float* __restrict__ Wl, const float* __restrict__ bl,
        const float* __restrict__ Wr,
        float* __restrict__ h_out)
{
    __shared__ __align__(16) float sWl[1024], sWr[1024];
    __shared__ float sbl[32];
    int tid = threadIdx.x;
    for (int j = tid; j < 1024; j += 256) { sWl[j] = Wl[j]; sWr[j] = Wr[j]; }
    if (tid < 32) sbl[tid] = bl[tid];
    __syncthreads();

    int n = blockIdx.x * 256 + tid;
    if (n >= N_SW) return;

    u64 acc[16];
#pragma unroll
    for (int jj = 0; jj < 16; jj++) acc[jj] = pk2f(sbl[2 * jj], sbl[2 * jj + 1]);

    float inv = 1.0f / fmaxf(g_cnt_ps[n], 1.0f);
    float xr[32];
    load_row(g_sum_ps, n, inv, xr);
    mv_acc(sWl, xr, acc);
    load_row(x_sw, n, 1.0f, xr);
    mv_acc(sWr, xr, acc);

    float4* o4 = (float4*)(h_out + (size_t)n * D);
#pragma unroll
    for (int q = 0; q < 8; q++) {
        float2 a = up2(acc[2 * q]);
        float2 b = up2(acc[2 * q + 1]);
        o4[q] = make_float4(fmaxf(a.x, 0.f), fmaxf(a.y, 0.f),
                            fmaxf(b.x, 0.f), fmaxf(b.y, 0.f));
    }
}

// ---------------------------------------------------------------------------
// Launch
// ---------------------------------------------------------------------------
extern "C" void kernel_launch(void* const* d_in, const int* in_sizes, int n_in,
                              void* d_out, int out_size)
{
    const float* x_pfas = (const float*)d_in[0];
    const float* x_gw   = (const float*)d_in[1];
    const float* x_sw   = (const float*)d_in[2];
    const int*   src_pg = (const int*)d_in[3];
    const int*   dst_pg = (const int*)d_in[4];
    const float* ea_pg  = (const float*)d_in[5];
    const int*   src_gp = (const int*)d_in[6];
    const int*   dst_gp = (const int*)d_in[7];
    const float* ea_gp  = (const float*)d_in[8];
    const int*   src_ps = (const int*)d_in[9];
    const int*   dst_ps = (const int*)d_in[10];
    const int*   src_sp = (const int*)d_in[11];
    const int*   dst_sp = (const int*)d_in[12];
    const float* Wl_pg  = (const float*)d_in[13];
    const float* bl_pg  = (const float*)d_in[14];
    const float* Wr_pg  = (const float*)d_in[15];
    const float* We_pg  = (const float*)d_in[16];
    const float* be_pg  = (const float*)d_in[17];
    const float* Wl_gp  = (const float*)d_in[18];
    const float* bl_gp  = (const float*)d_in[19];
    const float* Wr_gp  = (const float*)d_in[20];
    const float* We_gp  = (const float*)d_in[21];
    const float* be_gp  = (const float*)d_in[22];
    const float* Wl_ps  = (const float*)d_in[23];
    const float* bl_ps  = (const float*)d_in[24];
    const float* Wr_ps  = (const float*)d_in[25];
    const float* Wl_sp  = (const float*)d_in[26];
    const float* bl_sp  = (const float*)d_in[27];
    const float* Wr_sp  = (const float*)d_in[28];
    const float* W_out  = (const float*)d_in[29];
    const float* b_out  = (const float*)d_in[30];
    const float* a_pre  = (const float*)d_in[31];

    float* out      = (float*)d_out;
    float* out_pfas = out;
    float* out_y    = out + OFF_Y;
    float* out_sw   = out + OFF_SW;

    float *p_sum_pg, *p_cnt_pg, *p_sum_gp, *p_cnt_gp, *p_sum_sp, *p_cnt_sp, *p_sum_ps, *p_cnt_ps;
    int *p_maxe_pg, *p_maxe_gp;
    cudaGetSymbolAddress((void**)&p_sum_pg, g_sum_pg);
    cudaGetSymbolAddress((void**)&p_cnt_pg, g_cnt_pg);
    cudaGetSymbolAddress((void**)&p_sum_gp, g_sum_gp);
    cudaGetSymbolAddress((void**)&p_cnt_gp, g_cnt_gp);
    cudaGetSymbolAddress((void**)&p_sum_sp, g_sum_sp);
    cudaGetSymbolAddress((void**)&p_cnt_sp, g_cnt_sp);
    cudaGetSymbolAddress((void**)&p_sum_ps, g_sum_ps);
    cudaGetSymbolAddress((void**)&p_cnt_ps, g_cnt_ps);
    cudaGetSymbolAddress((void**)&p_maxe_pg, g_maxe_pg);
    cudaGetSymbolAddress((void**)&p_maxe_gp, g_maxe_gp);

    // 1) init scratch
    k_init<<<2048, 256>>>();

    // 2) fused edge aggregation: 4 relations, 4 edges per 8-lane group
    {
        AggArgs A;
        const float* xs[4]  = { x_pfas, x_gw, x_sw, x_pfas };
        const int*   ss[4]  = { src_pg, src_gp, src_sp, src_ps };
        const int*   ds[4]  = { dst_pg, dst_gp, dst_sp, dst_ps };
        float*       sm[4]  = { p_sum_pg, p_sum_gp, p_sum_sp, p_sum_ps };
        float*       cn[4]  = { p_cnt_pg, p_cnt_gp, p_cnt_sp, p_cnt_ps };
        int*         mx[4]  = { p_maxe_pg, p_maxe_gp, nullptr, nullptr };
        int          Es[4]  = { E_PG, E_GP, E_SP, E_PS };
        int blocks = 0;
        for (int r = 0; r < 4; r++) {
            A.x[r]   = (const float4*)xs[r];
            A.src[r] = (const int4*)ss[r];
            A.dst[r] = (const int4*)ds[r];
            A.sum[r] = sm[r];
            A.cnt[r] = cn[r];
            A.maxe[r] = mx[r];
            int ng = Es[r] / 4;
            A.ngroups[r] = ng;
            int nthreads = ng * 8;
            blocks += (nthreads + 255) / 256;
            A.blkEnd[r] = blocks;
        }
        k_agg_all<<<blocks, 256>>>(A);
    }

    // 3) fused epilogues (thread per node, f32x2 matvecs)
    k_fin_gw<<<(N_GW + 255) / 256, 256>>>(x_gw, ea_pg,
                                          Wl_pg, bl_pg, Wr_pg, We_pg, be_pg,
                                          W_out, b_out, a_pre, out_y);
    k_fin_pfas<<<(N_PFAS + 255) / 256, 256>>>(x_pfas, ea_gp,
                                              Wl_gp, bl_gp, Wr_gp, We_gp, be_gp,
                                              Wl_sp, bl_sp, Wr_sp, out_pfas);
    k_fin_sw<<<(N_SW + 255) / 256, 256>>>(x_sw, Wl_ps, bl_ps, Wr_ps, out_sw);

    (void)in_sizes; (void)n_in; (void)out_size;
}

// round 4
// speedup vs baseline: 3.3278x; 1.0920x over previous
#include <cuda_runtime.h>

// ---------------------------------------------------------------------------
// Problem constants
// ---------------------------------------------------------------------------
#define N_PFAS 50000
#define N_GW   200000
#define N_SW   20000
#define D      32
#define E_PG   2000000
#define E_GP   2000000
#define E_PS   1000000
#define E_SP   1000000

#define OFF_Y   (N_PFAS * D)
#define OFF_SW  (N_PFAS * D + N_GW)

#define NB_GW  ((N_GW + 255) / 256)     // 782
#define NB_PF  ((N_PFAS + 255) / 256)   // 196
#define NB_SW  ((N_SW + 255) / 256)     // 79

typedef unsigned long long u64;

// ---------------------------------------------------------------------------
// Scratch (device globals; allocation-free). 16B aligned for v4 atomics/loads.
// ---------------------------------------------------------------------------
__device__ __align__(16) float g_sum_pg[(size_t)N_GW * D];
__device__ float g_cnt_pg[N_GW];
__device__ int   g_maxe_pg[N_GW];

__device__ __align__(16) float g_sum_gp[(size_t)N_PFAS * D];
__device__ float g_cnt_gp[N_PFAS];
__device__ int   g_maxe_gp[N_PFAS];

__device__ __align__(16) float g_sum_sp[(size_t)N_PFAS * D];
__device__ float g_cnt_sp[N_PFAS];

__device__ __align__(16) float g_sum_ps[(size_t)N_SW * D];
__device__ float g_cnt_ps[N_SW];

// ---------------------------------------------------------------------------
// Packed f32x2 helpers (sm_100+)
// ---------------------------------------------------------------------------
__device__ __forceinline__ u64 pk2(float x) {
    u64 d; unsigned xi = __float_as_uint(x);
    asm("mov.b64 %0, {%1, %1};" : "=l"(d) : "r"(xi));
    return d;
}
__device__ __forceinline__ u64 pk2f(float a, float b) {
    u64 d; unsigned ai = __float_as_uint(a), bi = __float_as_uint(b);
    asm("mov.b64 %0, {%1, %2};" : "=l"(d) : "r"(ai), "r"(bi));
    return d;
}
__device__ __forceinline__ u64 f2fma(u64 a, u64 b, u64 c) {
    u64 d; asm("fma.rn.f32x2 %0, %1, %2, %3;" : "=l"(d) : "l"(a), "l"(b), "l"(c));
    return d;
}
__device__ __forceinline__ u64 f2add(u64 a, u64 b) {
    u64 d; asm("add.rn.f32x2 %0, %1, %2;" : "=l"(d) : "l"(a), "l"(b));
    return d;
}
__device__ __forceinline__ float2 up2(u64 a) {
    unsigned lo, hi;
    asm("mov.b64 {%0, %1}, %2;" : "=r"(lo), "=r"(hi) : "l"(a));
    return make_float2(__uint_as_float(lo), __uint_as_float(hi));
}

// ---------------------------------------------------------------------------
// Vector atomic: red.global.add.v4.f32 (sm_90+)
// ---------------------------------------------------------------------------
__device__ __forceinline__ void red_add_v4(float* addr, float4 v) {
    asm volatile("red.global.add.v4.f32 [%0], {%1,%2,%3,%4};"
                 :: "l"(addr), "f"(v.x), "f"(v.y), "f"(v.z), "f"(v.w)
                 : "memory");
}

// ---------------------------------------------------------------------------
// Init
// ---------------------------------------------------------------------------
__global__ void k_init() {
    int i = blockIdx.x * blockDim.x + threadIdx.x;
    int stride = gridDim.x * blockDim.x;
    for (int j = i; j < N_GW * D;   j += stride) g_sum_pg[j] = 0.f;
    for (int j = i; j < N_PFAS * D; j += stride) g_sum_gp[j] = 0.f;
    for (int j = i; j < N_PFAS * D; j += stride) g_sum_sp[j] = 0.f;
    for (int j = i; j < N_SW * D;   j += stride) g_sum_ps[j] = 0.f;
    for (int j = i; j < N_GW;   j += stride) { g_cnt_pg[j] = 0.f; g_maxe_pg[j] = -1; }
    for (int j = i; j < N_PFAS; j += stride) { g_cnt_gp[j] = 0.f; g_maxe_gp[j] = -1;
                                               g_cnt_sp[j] = 0.f; }
    for (int j = i; j < N_SW;   j += stride) g_cnt_ps[j] = 0.f;
}

// ---------------------------------------------------------------------------
// Fused edge aggregation: all 4 relations in one launch.
// 8 lanes per edge-group; each group processes 4 consecutive edges (ILP=4).
// ---------------------------------------------------------------------------
struct AggArgs {
    const float4* x[4];
    const int4*   src[4];
    const int4*   dst[4];
    float*        sum[4];
    float*        cnt[4];
    int*          maxe[4];
    int           ngroups[4];
    int           blkEnd[4];
};

__global__ void k_agg_all(AggArgs A) {
    int b = blockIdx.x;
    int r, base;
    if (b < A.blkEnd[0])      { r = 0; base = 0; }
    else if (b < A.blkEnd[1]) { r = 1; base = A.blkEnd[0]; }
    else if (b < A.blkEnd[2]) { r = 2; base = A.blkEnd[1]; }
    else                      { r = 3; base = A.blkEnd[2]; }

    int t   = (b - base) * blockDim.x + threadIdx.x;
    int g   = t >> 3;
    int seg = t & 7;
    if (g >= A.ngroups[r]) return;

    int4 s4 = __ldg(&A.src[r][g]);
    int4 d4 = __ldg(&A.dst[r][g]);
    const float4* X = A.x[r];
    float* S = A.sum[r];

    float4 v0 = __ldg(&X[(size_t)s4.x * 8 + seg]);
    float4 v1 = __ldg(&X[(size_t)s4.y * 8 + seg]);
    float4 v2 = __ldg(&X[(size_t)s4.z * 8 + seg]);
    float4 v3 = __ldg(&X[(size_t)s4.w * 8 + seg]);

    red_add_v4(&S[(size_t)d4.x * D + seg * 4], v0);
    red_add_v4(&S[(size_t)d4.y * D + seg * 4], v1);
    red_add_v4(&S[(size_t)d4.z * D + seg * 4], v2);
    red_add_v4(&S[(size_t)d4.w * D + seg * 4], v3);

    if (seg == 0) {
        float* C = A.cnt[r];
        atomicAdd(&C[d4.x], 1.0f);
        atomicAdd(&C[d4.y], 1.0f);
        atomicAdd(&C[d4.z], 1.0f);
        atomicAdd(&C[d4.w], 1.0f);
        int* M = A.maxe[r];
        if (M) {
            int e0 = g * 4;
            atomicMax(&M[d4.x], e0);
            atomicMax(&M[d4.y], e0 + 1);
            atomicMax(&M[d4.z], e0 + 2);
            atomicMax(&M[d4.w], e0 + 3);
        }
    }
}

// ---------------------------------------------------------------------------
// Merged thread-per-node epilogue (one launch for GW + PFAS + SW)
// ---------------------------------------------------------------------------
__device__ __forceinline__ void load_row(const float* base, int n, float inv, float x[32]) {
    const float4* r4 = (const float4*)(base + (size_t)n * D);
#pragma unroll
    for (int q = 0; q < 8; q++) {
        float4 v = __ldg(&r4[q]);
        x[q * 4 + 0] = v.x * inv; x[q * 4 + 1] = v.y * inv;
        x[q * 4 + 2] = v.z * inv; x[q * 4 + 3] = v.w * inv;
    }
}

__device__ __forceinline__ void mv_acc(const float* sW, const float x[32], u64 acc[16]) {
#pragma unroll
    for (int k = 0; k < 32; k++) {
        u64 xk = pk2(x[k]);
        const u64* w2 = (const u64*)(sW + k * 32);
#pragma unroll
        for (int jj = 0; jj < 16; jj++) acc[jj] = f2fma(xk, w2[jj], acc[jj]);
    }
}

__device__ __forceinline__ void edge_acc(const float* __restrict__ ea, int me,
                                         const float* sWe, const float* sbe,
                                         u64 acc[16]) {
    u64 e0 = pk2(__ldg(&ea[3 * (size_t)me + 0]));
    u64 e1 = pk2(__ldg(&ea[3 * (size_t)me + 1]));
    u64 e2 = pk2(__ldg(&ea[3 * (size_t)me + 2]));
    const u64* w0 = (const u64*)(sWe);
    const u64* w1 = (const u64*)(sWe + 32);
    const u64* w2 = (const u64*)(sWe + 64);
#pragma unroll
    for (int jj = 0; jj < 16; jj++) {
        u64 a = acc[jj];
        a = f2fma(e0, w0[jj], a);
        a = f2fma(e1, w1[jj], a);
        a = f2fma(e2, w2[jj], a);
        a = f2add(a, pk2f(sbe[2 * jj], sbe[2 * jj + 1]));
        acc[jj] = a;
    }
}

struct FinArgs {
    const float *x_pfas, *x_gw, *x_sw;
    const float *ea_pg, *ea_gp;
    const float *Wl_pg, *bl_pg, *Wr_pg, *We_pg, *be_pg;
    const float *Wl_gp, *bl_gp, *Wr_gp, *We_gp, *be_gp;
    const float *Wl_ps, *bl_ps, *Wr_ps;
    const float *Wl_sp, *bl_sp, *Wr_sp;
    const float *W_out, *b_out, *a_pre;
    float *out_pfas, *out_y, *out_sw;
};

__global__ void __launch_bounds__(256) k_fin_all(FinArgs F) {
    __shared__ __align__(16) float sW[3 * 1024];
    __shared__ __align__(16) float sWe[96];
    __shared__ float sb[32], sbe[32], sWo[32];

    int b   = blockIdx.x;
    int tid = threadIdx.x;

    if (b < NB_GW) {
        // ---------------- GW phase ----------------
        for (int j = tid; j < 1024; j += 256) { sW[j] = F.Wl_pg[j]; sW[1024 + j] = F.Wr_pg[j]; }
        if (tid < 96) sWe[tid] = F.We_pg[tid];
        if (tid < 32) { sb[tid] = F.bl_pg[tid]; sbe[tid] = F.be_pg[tid]; sWo[tid] = F.W_out[tid]; }
        __syncthreads();

        int n = b * 256 + tid;
        if (n >= N_GW) return;

        u64 acc[16];
#pragma unroll
        for (int jj = 0; jj < 16; jj++) acc[jj] = pk2f(sb[2 * jj], sb[2 * jj + 1]);

        float inv = 1.0f / fmaxf(g_cnt_pg[n], 1.0f);
        float xr[32];
        load_row(g_sum_pg, n, inv, xr);
        mv_acc(sW, xr, acc);
        load_row(F.x_gw, n, 1.0f, xr);
        mv_acc(sW + 1024, xr, acc);

        int me = g_maxe_pg[n];
        if (me >= 0) edge_acc(F.ea_pg, me, sWe, sbe, acc);

        float yv = 0.0f;
#pragma unroll
        for (int jj = 0; jj < 16; jj++) {
            float2 h = up2(acc[jj]);
            yv += fmaxf(h.x, 0.0f) * sWo[2 * jj] + fmaxf(h.y, 0.0f) * sWo[2 * jj + 1];
        }
        yv += __ldg(&F.b_out[0]);
        float a_ = __ldg(&F.a_pre[0]);
        F.out_y[n] = (yv >= 0.0f) ? yv : a_ * yv;

    } else if (b < NB_GW + NB_PF) {
        // ---------------- PFAS phase ----------------
        for (int j = tid; j < 1024; j += 256) {
            sW[j]        = F.Wl_gp[j];
            sW[1024 + j] = F.Wl_sp[j];
            sW[2048 + j] = F.Wr_gp[j] + F.Wr_sp[j];
        }
        if (tid < 96) sWe[tid] = F.We_gp[tid];
        if (tid < 32) { sb[tid] = F.bl_gp[tid] + F.bl_sp[tid]; sbe[tid] = F.be_gp[tid]; }
        __syncthreads();

        int n = (b - NB_GW) * 256 + tid;
        if (n >= N_PFAS) return;

        u64 acc[16];
#pragma unroll
        for (int jj = 0; jj < 16; jj++) acc[jj] = pk2f(sb[2 * jj], sb[2 * jj + 1]);

        float invg = 1.0f / fmaxf(g_cnt_gp[n], 1.0f);
        float invs = 1.0f / fmaxf(g_cnt_sp[n], 1.0f);
        float xr[32];
        load_row(g_sum_gp, n, invg, xr);
        mv_acc(sW, xr, acc);
        load_row(g_sum_sp, n, invs, xr);
        mv_acc(sW + 1024, xr, acc);
        load_row(F.x_pfas, n, 1.0f, xr);
        mv_acc(sW + 2048, xr, acc);

        int me = g_maxe_gp[n];
        if (me >= 0) edge_acc(F.ea_gp, me, sWe, sbe, acc);

        float4* o4 = (float4*)(F.out_pfas + (size_t)n * D);
#pragma unroll
        for (int q = 0; q < 8; q++) {
            float2 a = up2(acc[2 * q]);
            float2 c = up2(acc[2 * q + 1]);
            o4[q] = make_float4(fmaxf(a.x, 0.f), fmaxf(a.y, 0.f),
                                fmaxf(c.x, 0.f), fmaxf(c.y, 0.f));
        }

    } else {
        // ---------------- SW phase ----------------
        for (int j = tid; j < 1024; j += 256) { sW[j] = F.Wl_ps[j]; sW[1024 + j] = F.Wr_ps[j]; }
        if (tid < 32) sb[tid] = F.bl_ps[tid];
        __syncthreads();

        int n = (b - NB_GW - NB_PF) * 256 + tid;
        if (n >= N_SW) return;

        u64 acc[16];
#pragma unroll
        for (int jj = 0; jj < 16; jj++) acc[jj] = pk2f(sb[2 * jj], sb[2 * jj + 1]);

        float inv = 1.0f / fmaxf(g_cnt_ps[n], 1.0f);
        float xr[32];
        load_row(g_sum_ps, n, inv, xr);
        mv_acc(sW, xr, acc);
        load_row(F.x_sw, n, 1.0f, xr);
        mv_acc(sW + 1024, xr, acc);

        float4* o4 = (float4*)(F.out_sw + (size_t)n * D);
#pragma unroll
        for (int q = 0; q < 8; q++) {
            float2 a = up2(acc[2 * q]);
            float2 c = up2(acc[2 * q + 1]);
            o4[q] = make_float4(fmaxf(a.x, 0.f), fmaxf(a.y, 0.f),
                                fmaxf(c.x, 0.f), fmaxf(c.y, 0.f));
        }
    }
}

// ---------------------------------------------------------------------------
// Launch
// ---------------------------------------------------------------------------
extern "C" void kernel_launch(void* const* d_in, const int* in_sizes, int n_in,
                              void* d_out, int out_size)
{
    const float* x_pfas = (const float*)d_in[0];
    const float* x_gw   = (const float*)d_in[1];
    const float* x_sw   = (const float*)d_in[2];
    const int*   src_pg = (const int*)d_in[3];
    const int*   dst_pg = (const int*)d_in[4];
    const float* ea_pg  = (const float*)d_in[5];
    const int*   src_gp = (const int*)d_in[6];
    const int*   dst_gp = (const int*)d_in[7];
    const float* ea_gp  = (const float*)d_in[8];
    const int*   src_ps = (const int*)d_in[9];
    const int*   dst_ps = (const int*)d_in[10];
    const int*   src_sp = (const int*)d_in[11];
    const int*   dst_sp = (const int*)d_in[12];

    float* out = (float*)d_out;

    float *p_sum_pg, *p_cnt_pg, *p_sum_gp, *p_cnt_gp, *p_sum_sp, *p_cnt_sp, *p_sum_ps, *p_cnt_ps;
    int *p_maxe_pg, *p_maxe_gp;
    cudaGetSymbolAddress((void**)&p_sum_pg, g_sum_pg);
    cudaGetSymbolAddress((void**)&p_cnt_pg, g_cnt_pg);
    cudaGetSymbolAddress((void**)&p_sum_gp, g_sum_gp);
    cudaGetSymbolAddress((void**)&p_cnt_gp, g_cnt_gp);
    cudaGetSymbolAddress((void**)&p_sum_sp, g_sum_sp);
    cudaGetSymbolAddress((void**)&p_cnt_sp, g_cnt_sp);
    cudaGetSymbolAddress((void**)&p_sum_ps, g_sum_ps);
    cudaGetSymbolAddress((void**)&p_cnt_ps, g_cnt_ps);
    cudaGetSymbolAddress((void**)&p_maxe_pg, g_maxe_pg);
    cudaGetSymbolAddress((void**)&p_maxe_gp, g_maxe_gp);

    // 1) init scratch
    k_init<<<2048, 256>>>();

    // 2) fused edge aggregation
    {
        AggArgs A;
        const float* xs[4]  = { x_pfas, x_gw, x_sw, x_pfas };
        const int*   ss[4]  = { src_pg, src_gp, src_sp, src_ps };
        const int*   ds[4]  = { dst_pg, dst_gp, dst_sp, dst_ps };
        float*       sm[4]  = { p_sum_pg, p_sum_gp, p_sum_sp, p_sum_ps };
        float*       cn[4]  = { p_cnt_pg, p_cnt_gp, p_cnt_sp, p_cnt_ps };
        int*         mx[4]  = { p_maxe_pg, p_maxe_gp, nullptr, nullptr };
        int          Es[4]  = { E_PG, E_GP, E_SP, E_PS };
        int blocks = 0;
        for (int r = 0; r < 4; r++) {
            A.x[r]   = (const float4*)xs[r];
            A.src[r] = (const int4*)ss[r];
            A.dst[r] = (const int4*)ds[r];
            A.sum[r] = sm[r];
            A.cnt[r] = cn[r];
            A.maxe[r] = mx[r];
            int ng = Es[r] / 4;
            A.ngroups[r] = ng;
            blocks += (ng * 8 + 255) / 256;
            A.blkEnd[r] = blocks;
        }
        k_agg_all<<<blocks, 256>>>(A);
    }

    // 3) merged epilogue (one launch)
    {
        FinArgs F;
        F.x_pfas = x_pfas; F.x_gw = x_gw; F.x_sw = x_sw;
        F.ea_pg = ea_pg;   F.ea_gp = ea_gp;
        F.Wl_pg = (const float*)d_in[13]; F.bl_pg = (const float*)d_in[14];
        F.Wr_pg = (const float*)d_in[15]; F.We_pg = (const float*)d_in[16];
        F.be_pg = (const float*)d_in[17];
        F.Wl_gp = (const float*)d_in[18]; F.bl_gp = (const float*)d_in[19];
        F.Wr_gp = (const float*)d_in[20]; F.We_gp = (const float*)d_in[21];
        F.be_gp = (const float*)d_in[22];
        F.Wl_ps = (const float*)d_in[23]; F.bl_ps = (const float*)d_in[24];
        F.Wr_ps = (const float*)d_in[25];
        F.Wl_sp = (const float*)d_in[26]; F.bl_sp = (const float*)d_in[27];
        F.Wr_sp = (const float*)d_in[28];
        F.W_out = (const float*)d_in[29]; F.b_out = (const float*)d_in[30];
        F.a_pre = (const float*)d_in[31];
        F.out_pfas = out;
        F.out_y    = out + OFF_Y;
        F.out_sw   = out + OFF_SW;

        k_fin_all<<<NB_GW + NB_PF + NB_SW, 256>>>(F);
    }

    (void)in_sizes; (void)n_in; (void)out_size;
}